// round 1
// baseline (speedup 1.0000x reference)
#include <cuda_runtime.h>
#include <math.h>

// Problem constants
#define Bc 2
#define Tc 2048
#define Cc 1024
#define Hc 16
#define Dc 64
#define NH (Bc * Hc)          // 32 (b,h) pairs
#define NJ 65                 // 2*MAXREL+1

// ---------------- scratch (device globals; no allocations allowed) ----------
__device__ float g_q[NH * Tc * Dc];    // [z][t][d]  z = b*H + h
__device__ float g_k[NH * Tc * Dc];
__device__ float g_v[NH * Tc * Dc];
__device__ float g_p[NH * Tc * NJ];    // P[z][t][j] = q(z,t) . rel_table[j]
__device__ float g_y[Bc * Tc * Cc];    // attention output in [B,T,C] layout

// ---------------- generic 128x128x8 SGEMM, K=1024 ---------------------------
// QKV=true : A = x (param), epilogue scatters into g_q/g_k/g_v head layout
// QKV=false: A = g_y (global), epilogue writes plain row-major out[m*N+n]
template <int N, bool QKV>
__global__ __launch_bounds__(256) void sgemm_kernel(
    const float* __restrict__ A_in, const float* __restrict__ W,
    const float* __restrict__ bias, float* __restrict__ out)
{
    constexpr int K = 1024;
    __shared__ float As[8][128];
    __shared__ float Bs[8][128];

    const float* A = QKV ? A_in : g_y;

    const int bn = blockIdx.x * 128;
    const int bm = blockIdx.y * 128;
    const int tid = threadIdx.x;

    const int aRow = tid >> 1;            // 0..127
    const int aCol = (tid & 1) << 2;      // 0 or 4
    const int bRow = tid >> 5;            // 0..7
    const int bCol = (tid & 31) << 2;     // 0..124

    const int tRow = (tid >> 4) << 3;     // 0..120
    const int tCol = (tid & 15) << 3;     // 0..120

    float acc[8][8] = {};

    const float* Ap = A + (size_t)(bm + aRow) * K + aCol;
    const float* Wp = W + (size_t)bRow * N + bn + bCol;

    for (int k0 = 0; k0 < K; k0 += 8) {
        float4 a4 = *(const float4*)Ap;
        As[aCol + 0][aRow] = a4.x;
        As[aCol + 1][aRow] = a4.y;
        As[aCol + 2][aRow] = a4.z;
        As[aCol + 3][aRow] = a4.w;
        *(float4*)&Bs[bRow][bCol] = *(const float4*)Wp;
        __syncthreads();

        #pragma unroll
        for (int kk = 0; kk < 8; kk++) {
            float4 a0 = *(const float4*)&As[kk][tRow];
            float4 a1 = *(const float4*)&As[kk][tRow + 4];
            float4 b0 = *(const float4*)&Bs[kk][tCol];
            float4 b1 = *(const float4*)&Bs[kk][tCol + 4];
            float ra[8] = {a0.x, a0.y, a0.z, a0.w, a1.x, a1.y, a1.z, a1.w};
            float rb[8] = {b0.x, b0.y, b0.z, b0.w, b1.x, b1.y, b1.z, b1.w};
            #pragma unroll
            for (int i = 0; i < 8; i++)
                #pragma unroll
                for (int j = 0; j < 8; j++)
                    acc[i][j] += ra[i] * rb[j];
        }
        __syncthreads();
        Ap += 8;
        Wp += (size_t)8 * N;
    }

    #pragma unroll
    for (int i = 0; i < 8; i++) {
        int m = bm + tRow + i;
        #pragma unroll
        for (int j = 0; j < 8; j++) {
            int n = bn + tCol + j;
            float v = acc[i][j] + bias[n];
            if (QKV) {
                int b = m >> 11;          // m / 2048
                int t = m & 2047;
                int sec = n >> 10;        // 0=q 1=k 2=v
                int c = n & 1023;
                int h = c >> 6;
                int d = c & 63;
                int z = b * Hc + h;
                float* dst = (sec == 0) ? g_q : (sec == 1 ? g_k : g_v);
                dst[((size_t)z * Tc + t) * Dc + d] = v;
            } else {
                out[(size_t)m * N + n] = v;
            }
        }
    }
}

// ---------------- P[z][t][j] = q(z,t) . rel_table[j] -------------------------
__global__ __launch_bounds__(256) void rel_p_kernel(const float* __restrict__ rel)
{
    int idx = blockIdx.x * 256 + threadIdx.x;
    if (idx >= NH * Tc * NJ) return;
    int j = idx % NJ;
    int row = idx / NJ;                  // z*T + t
    const float4* qp = (const float4*)(g_q + (size_t)row * Dc);
    const float4* rp = (const float4*)(rel + (size_t)j * Dc);
    float s = 0.f;
    #pragma unroll
    for (int d4 = 0; d4 < Dc / 4; d4++) {
        float4 a = qp[d4];
        float4 b = rp[d4];
        s += a.x * b.x + a.y * b.y + a.z * b.z + a.w * b.w;
    }
    g_p[idx] = s;
}

// ---------------- score tiles: att_raw = (QK^T + rel) * 0.125 ----------------
// grid (ktile, qtile, z); only lower-triangular tiles do work.
__global__ __launch_bounds__(256) void score_kernel(float* __restrict__ att)
{
    int kt = blockIdx.x, qt = blockIdx.y, z = blockIdx.z;
    if (kt > qt) return;

    __shared__ float Qs[Dc][65];   // [d][q_local]
    __shared__ float Ks[Dc][65];   // [d][k_local]

    int tid = threadIdx.x;
    int q0 = qt * 64, k0 = kt * 64;
    const float* qp = g_q + ((size_t)z * Tc + q0) * Dc;
    const float* kp = g_k + ((size_t)z * Tc + k0) * Dc;
    for (int i = tid; i < 64 * 64; i += 256) {
        int r = i >> 6, d = i & 63;
        Qs[d][r] = qp[(size_t)r * Dc + d];
        Ks[d][r] = kp[(size_t)r * Dc + d];
    }
    __syncthreads();

    int ty = tid >> 4, tx = tid & 15;
    int qr = ty * 4, kc = tx * 4;
    float acc[4][4] = {};
    #pragma unroll 8
    for (int d = 0; d < Dc; d++) {
        float a[4], b[4];
        #pragma unroll
        for (int i = 0; i < 4; i++) a[i] = Qs[d][qr + i];
        #pragma unroll
        for (int j = 0; j < 4; j++) b[j] = Ks[d][kc + j];
        #pragma unroll
        for (int i = 0; i < 4; i++)
            #pragma unroll
            for (int j = 0; j < 4; j++)
                acc[i][j] += a[i] * b[j];
    }

    #pragma unroll
    for (int i = 0; i < 4; i++) {
        int qg = q0 + qr + i;
        const float* Prow = g_p + ((size_t)z * Tc + qg) * NJ;
        float* orow = att + (((size_t)z * Tc + qg) * Tc);
        #pragma unroll
        for (int j = 0; j < 4; j++) {
            int kg = k0 + kc + j;
            if (kg <= qg) {
                int dd = kg - qg;                 // <= 0
                if (dd < -32) dd = -32;
                float v = (acc[i][j] + Prow[dd + 32]) * 0.125f;
                orow[kg] = v;
            }
        }
    }
}

// ---------------- row softmax (in place) + zero the masked upper part -------
__global__ __launch_bounds__(256) void softmax_kernel(float* __restrict__ att)
{
    int q = blockIdx.x, z = blockIdx.y;
    float* row = att + (((size_t)z * Tc + q) * Tc);
    int n = q + 1;

    __shared__ float srow[Tc];
    __shared__ float red[8];

    int tid = threadIdx.x;
    int lane = tid & 31, wid = tid >> 5;

    float m = -3.402823466e38f;
    for (int i = tid; i < n; i += 256) {
        float v = row[i];
        srow[i] = v;
        m = fmaxf(m, v);
    }
    #pragma unroll
    for (int o = 16; o > 0; o >>= 1) m = fmaxf(m, __shfl_xor_sync(0xffffffffu, m, o));
    if (lane == 0) red[wid] = m;
    __syncthreads();
    m = red[0];
    #pragma unroll
    for (int w = 1; w < 8; w++) m = fmaxf(m, red[w]);
    __syncthreads();

    float s = 0.f;
    for (int i = tid; i < n; i += 256) {
        float e = __expf(srow[i] - m);
        srow[i] = e;
        s += e;
    }
    #pragma unroll
    for (int o = 16; o > 0; o >>= 1) s += __shfl_xor_sync(0xffffffffu, s, o);
    if (lane == 0) red[wid] = s;
    __syncthreads();
    s = red[0];
    #pragma unroll
    for (int w = 1; w < 8; w++) s += red[w];

    float inv = 1.0f / s;
    for (int i = tid; i < n; i += 256) row[i] = srow[i] * inv;
    for (int i = n + tid; i < Tc; i += 256) row[i] = 0.f;
}

// ---------------- y = att @ V, written into [B,T,C] layout -------------------
__global__ __launch_bounds__(256) void av_kernel(const float* __restrict__ att)
{
    int qt = blockIdx.x, z = blockIdx.y;

    __shared__ float Ts[64][65];   // att transposed: [k_local][q_local]
    __shared__ float Vs[64][65];   // [k_local][d]

    int tid = threadIdx.x;
    int ty = tid >> 4, tx = tid & 15;
    int q0 = qt * 64;
    float acc[4][4] = {};

    for (int kt = 0; kt <= qt; kt++) {
        int k0 = kt * 64;
        const float* ap = att + (((size_t)z * Tc + q0) * Tc) + k0;
        const float* vp = g_v + ((size_t)z * Tc + k0) * Dc;
        for (int i = tid; i < 64 * 64; i += 256) {
            int r = i >> 6, c = i & 63;
            Ts[c][r] = ap[(size_t)r * Tc + c];
            Vs[r][c] = vp[(size_t)r * Dc + c];
        }
        __syncthreads();
        #pragma unroll 8
        for (int kk = 0; kk < 64; kk++) {
            float a[4], b[4];
            #pragma unroll
            for (int i = 0; i < 4; i++) a[i] = Ts[kk][ty * 4 + i];
            #pragma unroll
            for (int j = 0; j < 4; j++) b[j] = Vs[kk][tx * 4 + j];
            #pragma unroll
            for (int i = 0; i < 4; i++)
                #pragma unroll
                for (int j = 0; j < 4; j++)
                    acc[i][j] += a[i] * b[j];
        }
        __syncthreads();
    }

    int b = z / Hc, h = z % Hc;
    #pragma unroll
    for (int i = 0; i < 4; i++) {
        int qg = q0 + ty * 4 + i;
        #pragma unroll
        for (int j = 0; j < 4; j++) {
            int d = tx * 4 + j;
            g_y[(((size_t)b * Tc + qg) * Hc + h) * Dc + d] = acc[i][j];
        }
    }
}

// ---------------- launch ----------------------------------------------------
extern "C" void kernel_launch(void* const* d_in, const int* in_sizes, int n_in,
                              void* d_out, int out_size)
{
    const float* x      = (const float*)d_in[0];
    // d_in[1] = mask (causal tril) — structure hardcoded
    const float* w_attn = (const float*)d_in[2];
    const float* b_attn = (const float*)d_in[3];
    const float* w_proj = (const float*)d_in[4];
    const float* b_proj = (const float*)d_in[5];
    const float* rel    = (const float*)d_in[6];

    float* y_out = (float*)d_out;
    float* att   = y_out + (size_t)Bc * Tc * Cc;

    // 1) qkv = x @ w_attn + b_attn, scattered to head layout
    sgemm_kernel<3072, true><<<dim3(3072 / 128, 4096 / 128), 256>>>(x, w_attn, b_attn, nullptr);

    // 2) relative-position projections P[z,t,j]
    rel_p_kernel<<<(NH * Tc * NJ + 255) / 256, 256>>>(rel);

    // 3) raw masked scores into att output region
    score_kernel<<<dim3(Tc / 64, Tc / 64, NH), 256>>>(att);

    // 4) softmax rows in place (+ zero masked region)
    softmax_kernel<<<dim3(Tc, NH), 256>>>(att);

    // 5) y = att @ V  -> g_y in [B,T,C]
    av_kernel<<<dim3(Tc / 64, NH), 256>>>(att);

    // 6) out_y = g_y @ w_proj + b_proj
    sgemm_kernel<1024, false><<<dim3(1024 / 128, 4096 / 128), 256>>>(nullptr, w_proj, b_proj, y_out);
}

// round 3
// speedup vs baseline: 1.4629x; 1.4629x over previous
#include <cuda_runtime.h>
#include <cstdint>
#include <math.h>

// Problem constants
#define Bc 2
#define Tc 2048
#define Cc 1024
#define Hc 16
#define Dc 64
#define NH (Bc * Hc)          // 32 (b,h) pairs
#define NJ 65                 // 2*MAXREL+1

// ---------------- scratch (device globals; no allocations allowed) ----------
__device__ float g_q[NH * Tc * Dc];
__device__ float g_k[NH * Tc * Dc];
__device__ float g_v[NH * Tc * Dc];
__device__ float g_p[NH * Tc * NJ];
__device__ float g_y[Bc * Tc * Cc];
__device__ float g_wt[3072 * 1024];   // w_attn^T  [N=3072][K=1024]
__device__ float g_wtp[1024 * 1024];  // w_proj^T  [N=1024][K=1024]

// ======================= helpers ============================================
__device__ __forceinline__ uint32_t f2tf32(float f) {
    uint32_t r;
    asm("cvt.rna.tf32.f32 %0, %1;" : "=r"(r) : "f"(f));
    return r;
}
__device__ __forceinline__ void mma_tf32_16x8x8(
    float* c, const uint32_t* a, const uint32_t* b)
{
    asm volatile(
        "mma.sync.aligned.m16n8k8.row.col.f32.tf32.tf32.f32 "
        "{%0,%1,%2,%3}, {%4,%5,%6,%7}, {%8,%9}, {%0,%1,%2,%3};"
        : "+f"(c[0]), "+f"(c[1]), "+f"(c[2]), "+f"(c[3])
        : "r"(a[0]), "r"(a[1]), "r"(a[2]), "r"(a[3]), "r"(b[0]), "r"(b[1]));
}

// ======================= transpose: src[R][C] -> dst[C][R] ==================
__global__ __launch_bounds__(256) void transpose_kernel(
    const float* __restrict__ src, float* __restrict__ dst, int R, int C)
{
    __shared__ float t[32][33];
    int bx = blockIdx.x * 32, by = blockIdx.y * 32;
    int x = threadIdx.x, y0 = threadIdx.y;
    #pragma unroll
    for (int dy = 0; dy < 32; dy += 8)
        t[y0 + dy][x] = src[(size_t)(by + y0 + dy) * C + bx + x];
    __syncthreads();
    #pragma unroll
    for (int dy = 0; dy < 32; dy += 8)
        dst[(size_t)(bx + y0 + dy) * R + by + x] = t[x][y0 + dy];
}

// ======================= tf32 mma.sync GEMM =================================
// out[m][n] = sum_k A[m][k] * Bt[n][k] + bias[n]     (K = 1024)
// MODE 0: A = x (param), Bt = g_wt,  epilogue scatters qkv to g_q/g_k/g_v
// MODE 1: A = g_y,       Bt = g_wtp, epilogue writes out[m*1024+n]
// Block: 256 thr (8 warps, 2x4), tile 128x128, K-chunk 32, double buffered.
// smem (uint32 words): buf b at b*9216; A[128][36] then B[128][36].
#define GEMM_SMEM_BYTES (2 * 9216 * 4)
template <int N, int MODE>
__global__ __launch_bounds__(256) void mma_gemm(
    const float* __restrict__ A_in, const float* __restrict__ bias,
    float* __restrict__ out)
{
    extern __shared__ uint32_t sm[];
    const float* A  = (MODE == 0) ? A_in : g_y;
    const float* Bt = (MODE == 0) ? g_wt : g_wtp;

    const int tid = threadIdx.x, lane = tid & 31, wid = tid >> 5;
    const int bm = blockIdx.y * 128, bn = blockIdx.x * 128;
    const int wm = (wid >> 2) * 64, wn = (wid & 3) * 32;

    auto load_chunk = [&](int c, int b) {
        uint32_t* As = sm + b * 9216;
        uint32_t* Bs = As + 4608;
        const int k0 = c * 32;
        #pragma unroll
        for (int half = 0; half < 2; half++) {
            const float* src = half ? Bt + (size_t)bn * 1024 : A + (size_t)bm * 1024;
            uint32_t* dst = half ? Bs : As;
            #pragma unroll
            for (int it = 0; it < 4; it++) {
                int idx = it * 256 + tid;       // 1024 float4 per matrix
                int r = idx >> 3, q = idx & 7;
                float4 v = *(const float4*)(src + (size_t)r * 1024 + k0 + q * 4);
                uint4 u;
                u.x = f2tf32(v.x); u.y = f2tf32(v.y);
                u.z = f2tf32(v.z); u.w = f2tf32(v.w);
                *(uint4*)(dst + r * 36 + q * 4) = u;
            }
        }
    };

    float acc[4][4][4] = {};

    load_chunk(0, 0);
    __syncthreads();

    for (int c = 0; c < 32; c++) {
        int cur = c & 1;
        if (c + 1 < 32) load_chunk(c + 1, cur ^ 1);

        const uint32_t* As = sm + cur * 9216;
        const uint32_t* Bs = As + 4608;
        #pragma unroll
        for (int ks = 0; ks < 4; ks++) {
            const int kc = ks * 8 + (lane & 3);
            uint32_t a[4][4], b[4][2];
            #pragma unroll
            for (int mf = 0; mf < 4; mf++) {
                int row = wm + mf * 16 + (lane >> 2);
                a[mf][0] = As[row * 36 + kc];
                a[mf][1] = As[(row + 8) * 36 + kc];
                a[mf][2] = As[row * 36 + kc + 4];
                a[mf][3] = As[(row + 8) * 36 + kc + 4];
            }
            #pragma unroll
            for (int nf = 0; nf < 4; nf++) {
                int col = wn + nf * 8 + (lane >> 2);
                b[nf][0] = Bs[col * 36 + kc];
                b[nf][1] = Bs[col * 36 + kc + 4];
            }
            #pragma unroll
            for (int mf = 0; mf < 4; mf++)
                #pragma unroll
                for (int nf = 0; nf < 4; nf++)
                    mma_tf32_16x8x8(acc[mf][nf], a[mf], b[nf]);
        }
        __syncthreads();
    }

    // epilogue
    #pragma unroll
    for (int mf = 0; mf < 4; mf++) {
        #pragma unroll
        for (int nf = 0; nf < 4; nf++) {
            #pragma unroll
            for (int e = 0; e < 4; e++) {
                int m = bm + wm + mf * 16 + (lane >> 2) + (e >= 2 ? 8 : 0);
                int n = bn + wn + nf * 8 + 2 * (lane & 3) + (e & 1);
                float v = acc[mf][nf][e] + bias[n];
                if (MODE == 0) {
                    int b = m >> 11;
                    int t = m & 2047;
                    int sec = n >> 10;        // 0=q 1=k 2=v
                    int cc = n & 1023;
                    int h = cc >> 6;
                    int d = cc & 63;
                    int z = b * Hc + h;
                    float* dst = (sec == 0) ? g_q : (sec == 1 ? g_k : g_v);
                    dst[((size_t)z * Tc + t) * Dc + d] = v;
                } else {
                    out[(size_t)m * 1024 + n] = v;
                }
            }
        }
    }
}

// ---------------- P[z][t][j] = q(z,t) . rel_table[j] -------------------------
__global__ __launch_bounds__(256) void rel_p_kernel(const float* __restrict__ rel)
{
    int idx = blockIdx.x * 256 + threadIdx.x;
    if (idx >= NH * Tc * NJ) return;
    int j = idx % NJ;
    int row = idx / NJ;
    const float4* qp = (const float4*)(g_q + (size_t)row * Dc);
    const float4* rp = (const float4*)(rel + (size_t)j * Dc);
    float s = 0.f;
    #pragma unroll
    for (int d4 = 0; d4 < Dc / 4; d4++) {
        float4 a = qp[d4];
        float4 b = rp[d4];
        s += a.x * b.x + a.y * b.y + a.z * b.z + a.w * b.w;
    }
    g_p[idx] = s;
}

// ---------------- score tiles: att_raw = (QK^T + rel) * 0.125 ----------------
__global__ __launch_bounds__(256) void score_kernel(float* __restrict__ att)
{
    int kt = blockIdx.x, qt = blockIdx.y, z = blockIdx.z;
    if (kt > qt) return;

    __shared__ float Qs[Dc][65];
    __shared__ float Ks[Dc][65];

    int tid = threadIdx.x;
    int q0 = qt * 64, k0 = kt * 64;
    const float* qp = g_q + ((size_t)z * Tc + q0) * Dc;
    const float* kp = g_k + ((size_t)z * Tc + k0) * Dc;
    for (int i = tid; i < 64 * 64; i += 256) {
        int r = i >> 6, d = i & 63;
        Qs[d][r] = qp[(size_t)r * Dc + d];
        Ks[d][r] = kp[(size_t)r * Dc + d];
    }
    __syncthreads();

    int ty = tid >> 4, tx = tid & 15;
    int qr = ty * 4, kc = tx * 4;
    float acc[4][4] = {};
    #pragma unroll 8
    for (int d = 0; d < Dc; d++) {
        float a[4], b[4];
        #pragma unroll
        for (int i = 0; i < 4; i++) a[i] = Qs[d][qr + i];
        #pragma unroll
        for (int j = 0; j < 4; j++) b[j] = Ks[d][kc + j];
        #pragma unroll
        for (int i = 0; i < 4; i++)
            #pragma unroll
            for (int j = 0; j < 4; j++)
                acc[i][j] += a[i] * b[j];
    }

    #pragma unroll
    for (int i = 0; i < 4; i++) {
        int qg = q0 + qr + i;
        const float* Prow = g_p + ((size_t)z * Tc + qg) * NJ;
        float* orow = att + (((size_t)z * Tc + qg) * Tc);
        #pragma unroll
        for (int j = 0; j < 4; j++) {
            int kg = k0 + kc + j;
            if (kg <= qg) {
                int dd = kg - qg;
                if (dd < -32) dd = -32;
                orow[kg] = (acc[i][j] + Prow[dd + 32]) * 0.125f;
            }
        }
    }
}

// ---------------- row softmax (in place) + zero the masked upper part -------
__global__ __launch_bounds__(256) void softmax_kernel(float* __restrict__ att)
{
    int q = blockIdx.x, z = blockIdx.y;
    float* row = att + (((size_t)z * Tc + q) * Tc);
    int n = q + 1;

    __shared__ float srow[Tc];
    __shared__ float red[8];

    int tid = threadIdx.x;
    int lane = tid & 31, wid = tid >> 5;

    float m = -3.402823466e38f;
    for (int i = tid; i < n; i += 256) {
        float v = row[i];
        srow[i] = v;
        m = fmaxf(m, v);
    }
    #pragma unroll
    for (int o = 16; o > 0; o >>= 1) m = fmaxf(m, __shfl_xor_sync(0xffffffffu, m, o));
    if (lane == 0) red[wid] = m;
    __syncthreads();
    m = red[0];
    #pragma unroll
    for (int w = 1; w < 8; w++) m = fmaxf(m, red[w]);
    __syncthreads();

    float s = 0.f;
    for (int i = tid; i < n; i += 256) {
        float e = __expf(srow[i] - m);
        srow[i] = e;
        s += e;
    }
    #pragma unroll
    for (int o = 16; o > 0; o >>= 1) s += __shfl_xor_sync(0xffffffffu, s, o);
    if (lane == 0) red[wid] = s;
    __syncthreads();
    s = red[0];
    #pragma unroll
    for (int w = 1; w < 8; w++) s += red[w];

    float inv = 1.0f / s;
    for (int i = tid; i < n; i += 256) row[i] = srow[i] * inv;
    for (int i = n + tid; i < Tc; i += 256) row[i] = 0.f;
}

// ---------------- y = att @ V, written into [B,T,C] layout -------------------
__global__ __launch_bounds__(256) void av_kernel(const float* __restrict__ att)
{
    int qt = blockIdx.x, z = blockIdx.y;

    __shared__ float Ts[64][65];
    __shared__ float Vs[64][65];

    int tid = threadIdx.x;
    int ty = tid >> 4, tx = tid & 15;
    int q0 = qt * 64;
    float acc[4][4] = {};

    for (int kt = 0; kt <= qt; kt++) {
        int k0 = kt * 64;
        const float* ap = att + (((size_t)z * Tc + q0) * Tc) + k0;
        const float* vp = g_v + ((size_t)z * Tc + k0) * Dc;
        for (int i = tid; i < 64 * 64; i += 256) {
            int r = i >> 6, c = i & 63;
            Ts[c][r] = ap[(size_t)r * Tc + c];
            Vs[r][c] = vp[(size_t)r * Dc + c];
        }
        __syncthreads();
        #pragma unroll 8
        for (int kk = 0; kk < 64; kk++) {
            float a[4], b[4];
            #pragma unroll
            for (int i = 0; i < 4; i++) a[i] = Ts[kk][ty * 4 + i];
            #pragma unroll
            for (int j = 0; j < 4; j++) b[j] = Vs[kk][tx * 4 + j];
            #pragma unroll
            for (int i = 0; i < 4; i++)
                #pragma unroll
                for (int j = 0; j < 4; j++)
                    acc[i][j] += a[i] * b[j];
        }
        __syncthreads();
    }

    int b = z / Hc, h = z % Hc;
    #pragma unroll
    for (int i = 0; i < 4; i++) {
        int qg = q0 + ty * 4 + i;
        #pragma unroll
        for (int j = 0; j < 4; j++) {
            int d = tx * 4 + j;
            g_y[(((size_t)b * Tc + qg) * Hc + h) * Dc + d] = acc[i][j];
        }
    }
}

// ---------------- launch ----------------------------------------------------
extern "C" void kernel_launch(void* const* d_in, const int* in_sizes, int n_in,
                              void* d_out, int out_size)
{
    const float* x      = (const float*)d_in[0];
    const float* w_attn = (const float*)d_in[2];
    const float* b_attn = (const float*)d_in[3];
    const float* w_proj = (const float*)d_in[4];
    const float* b_proj = (const float*)d_in[5];
    const float* rel    = (const float*)d_in[6];

    float* y_out = (float*)d_out;
    float* att   = y_out + (size_t)Bc * Tc * Cc;

    cudaFuncSetAttribute(mma_gemm<3072, 0>, cudaFuncAttributeMaxDynamicSharedMemorySize, GEMM_SMEM_BYTES);
    cudaFuncSetAttribute(mma_gemm<1024, 1>, cudaFuncAttributeMaxDynamicSharedMemorySize, GEMM_SMEM_BYTES);

    float* wt  = nullptr;
    float* wtp = nullptr;
    cudaGetSymbolAddress((void**)&wt, g_wt);
    cudaGetSymbolAddress((void**)&wtp, g_wtp);

    // 0) transpose weights to [N][K] K-major
    transpose_kernel<<<dim3(3072 / 32, 1024 / 32), dim3(32, 8)>>>(w_attn, wt, 1024, 3072);
    transpose_kernel<<<dim3(1024 / 32, 1024 / 32), dim3(32, 8)>>>(w_proj, wtp, 1024, 1024);

    // 1) qkv = x @ w_attn + b_attn  (tf32 mma.sync), scattered to head layout
    mma_gemm<3072, 0><<<dim3(3072 / 128, 4096 / 128), 256, GEMM_SMEM_BYTES>>>(x, b_attn, nullptr);

    // 2) relative-position projections P[z,t,j]
    rel_p_kernel<<<(NH * Tc * NJ + 255) / 256, 256>>>(rel);

    // 3) raw masked scores into att output region
    score_kernel<<<dim3(Tc / 64, Tc / 64, NH), 256>>>(att);

    // 4) softmax rows in place (+ zero masked region)
    softmax_kernel<<<dim3(Tc, NH), 256>>>(att);

    // 5) y = att @ V  -> g_y in [B,T,C]
    av_kernel<<<dim3(Tc / 64, NH), 256>>>(att);

    // 6) out_y = g_y @ w_proj + b_proj  (tf32 mma.sync)
    mma_gemm<1024, 1><<<dim3(1024 / 128, 4096 / 128), 256, GEMM_SMEM_BYTES>>>(nullptr, b_proj, y_out);
}

// round 5
// speedup vs baseline: 2.5552x; 1.7466x over previous
#include <cuda_runtime.h>
#include <cstdint>
#include <math.h>

// Problem constants
#define Bc 2
#define Tc 2048
#define Cc 1024
#define Hc 16
#define Dc 64
#define NH (Bc * Hc)          // 32 (b,h) pairs
#define NJP 33                // only offsets -32..0 occur under causal mask

// ---------------- scratch (device globals; no allocations allowed) ----------
__device__ float g_q[NH * Tc * Dc];
__device__ float g_k[NH * Tc * Dc];
__device__ float g_v[NH * Tc * Dc];
__device__ float g_p[NH * Tc * NJP];  // P[z][t][j], j in [0,32]
__device__ float g_y[Bc * Tc * Cc];
__device__ float g_wt[3072 * 1024];   // w_attn^T  [N=3072][K=1024]
__device__ float g_wtp[1024 * 1024];  // w_proj^T  [N=1024][K=1024]

// ======================= helpers ============================================
__device__ __forceinline__ uint32_t f2tf32(float f) {
    uint32_t r;
    asm("cvt.rna.tf32.f32 %0, %1;" : "=r"(r) : "f"(f));
    return r;
}
__device__ __forceinline__ void mma_tf32_16x8x8(
    float* c, const uint32_t* a, const uint32_t* b)
{
    asm volatile(
        "mma.sync.aligned.m16n8k8.row.col.f32.tf32.tf32.f32 "
        "{%0,%1,%2,%3}, {%4,%5,%6,%7}, {%8,%9}, {%0,%1,%2,%3};"
        : "+f"(c[0]), "+f"(c[1]), "+f"(c[2]), "+f"(c[3])
        : "r"(a[0]), "r"(a[1]), "r"(a[2]), "r"(a[3]), "r"(b[0]), "r"(b[1]));
}

// ======================= transpose: src[R][C] -> dst[C][R] ==================
__global__ __launch_bounds__(256) void transpose_kernel(
    const float* __restrict__ src, float* __restrict__ dst, int R, int C)
{
    __shared__ float t[32][33];
    int bx = blockIdx.x * 32, by = blockIdx.y * 32;
    int x = threadIdx.x, y0 = threadIdx.y;
    #pragma unroll
    for (int dy = 0; dy < 32; dy += 8)
        t[y0 + dy][x] = src[(size_t)(by + y0 + dy) * C + bx + x];
    __syncthreads();
    #pragma unroll
    for (int dy = 0; dy < 32; dy += 8)
        dst[(size_t)(bx + y0 + dy) * R + by + x] = t[x][y0 + dy];
}

// ======================= tf32 mma.sync GEMM (K=1024) ========================
// MODE 0: A = x (param), Bt = g_wt,  epilogue scatters qkv to g_q/g_k/g_v
// MODE 1: A = g_y,       Bt = g_wtp, epilogue writes out[m*1024+n]
#define GEMM_SMEM_BYTES (2 * 9216 * 4)
template <int N, int MODE>
__global__ __launch_bounds__(256) void mma_gemm(
    const float* __restrict__ A_in, const float* __restrict__ bias,
    float* __restrict__ out)
{
    extern __shared__ uint32_t sm[];
    const float* A  = (MODE == 0) ? A_in : g_y;
    const float* Bt = (MODE == 0) ? g_wt : g_wtp;

    const int tid = threadIdx.x, lane = tid & 31, wid = tid >> 5;
    const int bm = blockIdx.y * 128, bn = blockIdx.x * 128;
    const int wm = (wid >> 2) * 64, wn = (wid & 3) * 32;

    auto load_chunk = [&](int c, int b) {
        uint32_t* As = sm + b * 9216;
        uint32_t* Bs = As + 4608;
        const int k0 = c * 32;
        #pragma unroll
        for (int half = 0; half < 2; half++) {
            const float* src = half ? Bt + (size_t)bn * 1024 : A + (size_t)bm * 1024;
            uint32_t* dst = half ? Bs : As;
            #pragma unroll
            for (int it = 0; it < 4; it++) {
                int idx = it * 256 + tid;
                int r = idx >> 3, q = idx & 7;
                float4 v = *(const float4*)(src + (size_t)r * 1024 + k0 + q * 4);
                uint4 u;
                u.x = f2tf32(v.x); u.y = f2tf32(v.y);
                u.z = f2tf32(v.z); u.w = f2tf32(v.w);
                *(uint4*)(dst + r * 36 + q * 4) = u;
            }
        }
    };

    float acc[4][4][4] = {};

    load_chunk(0, 0);
    __syncthreads();

    for (int c = 0; c < 32; c++) {
        int cur = c & 1;
        if (c + 1 < 32) load_chunk(c + 1, cur ^ 1);

        const uint32_t* As = sm + cur * 9216;
        const uint32_t* Bs = As + 4608;
        #pragma unroll
        for (int ks = 0; ks < 4; ks++) {
            const int kc = ks * 8 + (lane & 3);
            uint32_t a[4][4], b[4][2];
            #pragma unroll
            for (int mf = 0; mf < 4; mf++) {
                int row = wm + mf * 16 + (lane >> 2);
                a[mf][0] = As[row * 36 + kc];
                a[mf][1] = As[(row + 8) * 36 + kc];
                a[mf][2] = As[row * 36 + kc + 4];
                a[mf][3] = As[(row + 8) * 36 + kc + 4];
            }
            #pragma unroll
            for (int nf = 0; nf < 4; nf++) {
                int col = wn + nf * 8 + (lane >> 2);
                b[nf][0] = Bs[col * 36 + kc];
                b[nf][1] = Bs[col * 36 + kc + 4];
            }
            #pragma unroll
            for (int mf = 0; mf < 4; mf++)
                #pragma unroll
                for (int nf = 0; nf < 4; nf++)
                    mma_tf32_16x8x8(acc[mf][nf], a[mf], b[nf]);
        }
        __syncthreads();
    }

    #pragma unroll
    for (int mf = 0; mf < 4; mf++) {
        #pragma unroll
        for (int nf = 0; nf < 4; nf++) {
            #pragma unroll
            for (int e = 0; e < 4; e++) {
                int m = bm + wm + mf * 16 + (lane >> 2) + (e >= 2 ? 8 : 0);
                int n = bn + wn + nf * 8 + 2 * (lane & 3) + (e & 1);
                float v = acc[mf][nf][e] + bias[n];
                if (MODE == 0) {
                    int b = m >> 11;
                    int t = m & 2047;
                    int sec = n >> 10;
                    int cc = n & 1023;
                    int h = cc >> 6;
                    int d = cc & 63;
                    int z = b * Hc + h;
                    float* dst = (sec == 0) ? g_q : (sec == 1 ? g_k : g_v);
                    dst[((size_t)z * Tc + t) * Dc + d] = v;
                } else {
                    out[(size_t)m * 1024 + n] = v;
                }
            }
        }
    }
}

// ---------------- P[z][t][j] = q(z,t) . rel_table[j], j in [0,32] -----------
__global__ __launch_bounds__(256) void rel_p_kernel(const float* __restrict__ rel)
{
    __shared__ float rs[NJP * Dc];
    int tid = threadIdx.x;
    for (int i = tid; i < NJP * Dc; i += 256) rs[i] = rel[i];
    __syncthreads();

    int row = blockIdx.x * 256 + tid;      // z*T + t
    float4 qv[16];
    const float4* qp = (const float4*)(g_q + (size_t)row * Dc);
    #pragma unroll
    for (int i = 0; i < 16; i++) qv[i] = qp[i];

    #pragma unroll 1
    for (int j = 0; j < NJP; j++) {
        const float4* rp = (const float4*)(rs + j * Dc);
        float s = 0.f;
        #pragma unroll
        for (int i = 0; i < 16; i++) {
            float4 b = rp[i];
            s += qv[i].x * b.x + qv[i].y * b.y + qv[i].z * b.z + qv[i].w * b.w;
        }
        g_p[(size_t)row * NJP + j] = s;
    }
}

// ---------------- score: att = causal((QK^T + rel) * 0.125), tf32 mma -------
// 128x128 tiles; strictly-upper tiles write zeros (softmax then skips them).
#define SCORE_SMEM_BYTES ((2 * 128 * 68 + 128 * 34) * 4)
__global__ __launch_bounds__(256) void score_mma(float* __restrict__ att)
{
    const int kt = blockIdx.x, qt = blockIdx.y, z = blockIdx.z;
    const int q0 = qt * 128, k0 = kt * 128;
    const int tid = threadIdx.x;

    if (kt > qt) {
        float4 zz = make_float4(0.f, 0.f, 0.f, 0.f);
        #pragma unroll
        for (int it = 0; it < 16; it++) {
            int idx = it * 256 + tid;
            int r = idx >> 5, c = idx & 31;
            *(float4*)(att + ((size_t)z * Tc + q0 + r) * Tc + k0 + c * 4) = zz;
        }
        return;
    }

    extern __shared__ uint32_t sm[];
    uint32_t* Qs = sm;                         // [128][68]
    uint32_t* Ks = sm + 128 * 68;              // [128][68]
    float*    Ps = (float*)(sm + 2 * 128 * 68); // [128][34]

    const int lane = tid & 31, wid = tid >> 5;
    const float* qg = g_q + ((size_t)z * Tc + q0) * Dc;
    const float* kg = g_k + ((size_t)z * Tc + k0) * Dc;
    #pragma unroll
    for (int it = 0; it < 8; it++) {
        int idx = it * 256 + tid;
        int r = idx >> 4, c4 = idx & 15;
        float4 v = *(const float4*)(qg + (size_t)r * Dc + c4 * 4);
        *(uint4*)(Qs + r * 68 + c4 * 4) =
            make_uint4(f2tf32(v.x), f2tf32(v.y), f2tf32(v.z), f2tf32(v.w));
        float4 w = *(const float4*)(kg + (size_t)r * Dc + c4 * 4);
        *(uint4*)(Ks + r * 68 + c4 * 4) =
            make_uint4(f2tf32(w.x), f2tf32(w.y), f2tf32(w.z), f2tf32(w.w));
    }
    for (int i = tid; i < 128 * NJP; i += 256) {
        int r = i / NJP, j = i - r * NJP;
        Ps[r * 34 + j] = g_p[((size_t)z * Tc + q0 + r) * NJP + j];
    }
    __syncthreads();

    const int wm = (wid >> 2) * 64, wn = (wid & 3) * 32;
    float acc[4][4][4] = {};
    #pragma unroll
    for (int ks = 0; ks < 8; ks++) {
        const int kc = ks * 8 + (lane & 3);
        uint32_t a[4][4], b[4][2];
        #pragma unroll
        for (int mf = 0; mf < 4; mf++) {
            int row = wm + mf * 16 + (lane >> 2);
            a[mf][0] = Qs[row * 68 + kc];
            a[mf][1] = Qs[(row + 8) * 68 + kc];
            a[mf][2] = Qs[row * 68 + kc + 4];
            a[mf][3] = Qs[(row + 8) * 68 + kc + 4];
        }
        #pragma unroll
        for (int nf = 0; nf < 4; nf++) {
            int col = wn + nf * 8 + (lane >> 2);
            b[nf][0] = Ks[col * 68 + kc];
            b[nf][1] = Ks[col * 68 + kc + 4];
        }
        #pragma unroll
        for (int mf = 0; mf < 4; mf++)
            #pragma unroll
            for (int nf = 0; nf < 4; nf++)
                mma_tf32_16x8x8(acc[mf][nf], a[mf], b[nf]);
    }

    #pragma unroll
    for (int mf = 0; mf < 4; mf++) {
        #pragma unroll
        for (int nf = 0; nf < 4; nf++) {
            #pragma unroll
            for (int e = 0; e < 4; e++) {
                int row_l = wm + mf * 16 + (lane >> 2) + (e >= 2 ? 8 : 0);
                int col_l = wn + nf * 8 + 2 * (lane & 3) + (e & 1);
                int qq = q0 + row_l, kk = k0 + col_l;
                float v = 0.f;
                if (kk <= qq) {
                    int dd = kk - qq;
                    if (dd < -32) dd = -32;
                    v = (acc[mf][nf][e] + Ps[row_l * 34 + dd + 32]) * 0.125f;
                }
                att[((size_t)z * Tc + qq) * Tc + kk] = v;
            }
        }
    }
}

// ---------------- row softmax (in place, causal part only) ------------------
__global__ __launch_bounds__(256) void softmax_kernel(float* __restrict__ att)
{
    int q = blockIdx.x, z = blockIdx.y;
    float* row = att + (((size_t)z * Tc + q) * Tc);
    int n = q + 1;

    __shared__ float srow[Tc];
    __shared__ float red[8];

    int tid = threadIdx.x;
    int lane = tid & 31, wid = tid >> 5;

    float m = -3.402823466e38f;
    for (int i = tid; i < n; i += 256) {
        float v = row[i];
        srow[i] = v;
        m = fmaxf(m, v);
    }
    #pragma unroll
    for (int o = 16; o > 0; o >>= 1) m = fmaxf(m, __shfl_xor_sync(0xffffffffu, m, o));
    if (lane == 0) red[wid] = m;
    __syncthreads();
    m = red[0];
    #pragma unroll
    for (int w = 1; w < 8; w++) m = fmaxf(m, red[w]);
    __syncthreads();

    float s = 0.f;
    for (int i = tid; i < n; i += 256) {
        float e = __expf(srow[i] - m);
        srow[i] = e;
        s += e;
    }
    #pragma unroll
    for (int o = 16; o > 0; o >>= 1) s += __shfl_xor_sync(0xffffffffu, s, o);
    if (lane == 0) red[wid] = s;
    __syncthreads();
    s = red[0];
    #pragma unroll
    for (int w = 1; w < 8; w++) s += red[w];

    float inv = 1.0f / s;
    for (int i = tid; i < n; i += 256) row[i] = srow[i] * inv;
}

// ---------------- y = att @ V (tf32 mma), -> g_y [B,T,C] --------------------
// att upper triangle is exact zeros, so full tiles need no masking.
#define AV_SMEM_BYTES ((128 * 132 + 64 * 132) * 4)
__global__ __launch_bounds__(256) void av_mma(const float* __restrict__ att)
{
    const int qt = blockIdx.x, z = blockIdx.y;
    extern __shared__ uint32_t sm[];
    uint32_t* As = sm;               // [128][132]  att tile, k-major
    uint32_t* Vs = sm + 128 * 132;   // [64][132]   V^T tile: [d][k]

    const int tid = threadIdx.x, lane = tid & 31, wid = tid >> 5;
    const int q0 = qt * 128;
    const int wm = (wid >> 1) * 32, wn = (wid & 1) * 32;
    float acc[2][4][4] = {};

    for (int kt = 0; kt <= qt; kt++) {
        const int k0 = kt * 128;
        const float* ag = att + ((size_t)z * Tc + q0) * Tc + k0;
        const float* vg = g_v + ((size_t)z * Tc + k0) * Dc;
        #pragma unroll
        for (int it = 0; it < 16; it++) {
            int idx = it * 256 + tid;
            int r = idx >> 5, c4 = idx & 31;
            float4 v = *(const float4*)(ag + (size_t)r * Tc + c4 * 4);
            *(uint4*)(As + r * 132 + c4 * 4) =
                make_uint4(f2tf32(v.x), f2tf32(v.y), f2tf32(v.z), f2tf32(v.w));
        }
        #pragma unroll
        for (int it = 0; it < 8; it++) {
            int idx = it * 256 + tid;
            int r = idx >> 4, c4 = idx & 15;   // r = k-row, c4 = d-group
            float4 v = *(const float4*)(vg + (size_t)r * Dc + c4 * 4);
            Vs[(c4 * 4 + 0) * 132 + r] = f2tf32(v.x);
            Vs[(c4 * 4 + 1) * 132 + r] = f2tf32(v.y);
            Vs[(c4 * 4 + 2) * 132 + r] = f2tf32(v.z);
            Vs[(c4 * 4 + 3) * 132 + r] = f2tf32(v.w);
        }
        __syncthreads();

        #pragma unroll
        for (int ks = 0; ks < 16; ks++) {
            const int kc = ks * 8 + (lane & 3);
            uint32_t a[2][4], b[4][2];
            #pragma unroll
            for (int mf = 0; mf < 2; mf++) {
                int row = wm + mf * 16 + (lane >> 2);
                a[mf][0] = As[row * 132 + kc];
                a[mf][1] = As[(row + 8) * 132 + kc];
                a[mf][2] = As[row * 132 + kc + 4];
                a[mf][3] = As[(row + 8) * 132 + kc + 4];
            }
            #pragma unroll
            for (int nf = 0; nf < 4; nf++) {
                int col = wn + nf * 8 + (lane >> 2);
                b[nf][0] = Vs[col * 132 + kc];
                b[nf][1] = Vs[col * 132 + kc + 4];
            }
            #pragma unroll
            for (int mf = 0; mf < 2; mf++)
                #pragma unroll
                for (int nf = 0; nf < 4; nf++)
                    mma_tf32_16x8x8(acc[mf][nf], a[mf], b[nf]);
        }
        __syncthreads();
    }

    const int b_ = z / Hc, h = z % Hc;
    #pragma unroll
    for (int mf = 0; mf < 2; mf++) {
        #pragma unroll
        for (int nf = 0; nf < 4; nf++) {
            #pragma unroll
            for (int e = 0; e < 4; e++) {
                int row_l = wm + mf * 16 + (lane >> 2) + (e >= 2 ? 8 : 0);
                int d = wn + nf * 8 + 2 * (lane & 3) + (e & 1);
                int q = q0 + row_l;
                g_y[(((size_t)b_ * Tc + q) * Hc + h) * Dc + d] = acc[mf][nf][e];
            }
        }
    }
}

// ---------------- launch ----------------------------------------------------
extern "C" void kernel_launch(void* const* d_in, const int* in_sizes, int n_in,
                              void* d_out, int out_size)
{
    const float* x      = (const float*)d_in[0];
    const float* w_attn = (const float*)d_in[2];
    const float* b_attn = (const float*)d_in[3];
    const float* w_proj = (const float*)d_in[4];
    const float* b_proj = (const float*)d_in[5];
    const float* rel    = (const float*)d_in[6];

    float* y_out = (float*)d_out;
    float* att   = y_out + (size_t)Bc * Tc * Cc;

    cudaFuncSetAttribute(mma_gemm<3072, 0>, cudaFuncAttributeMaxDynamicSharedMemorySize, GEMM_SMEM_BYTES);
    cudaFuncSetAttribute(mma_gemm<1024, 1>, cudaFuncAttributeMaxDynamicSharedMemorySize, GEMM_SMEM_BYTES);
    cudaFuncSetAttribute(score_mma, cudaFuncAttributeMaxDynamicSharedMemorySize, SCORE_SMEM_BYTES);
    cudaFuncSetAttribute(av_mma, cudaFuncAttributeMaxDynamicSharedMemorySize, AV_SMEM_BYTES);

    float* wt  = nullptr;
    float* wtp = nullptr;
    cudaGetSymbolAddress((void**)&wt, g_wt);
    cudaGetSymbolAddress((void**)&wtp, g_wtp);

    // 0) transpose weights to [N][K] K-major
    transpose_kernel<<<dim3(3072 / 32, 1024 / 32), dim3(32, 8)>>>(w_attn, wt, 1024, 3072);
    transpose_kernel<<<dim3(1024 / 32, 1024 / 32), dim3(32, 8)>>>(w_proj, wtp, 1024, 1024);

    // 1) qkv = x @ w_attn + b_attn  (tf32 mma), scattered to head layout
    mma_gemm<3072, 0><<<dim3(3072 / 128, 4096 / 128), 256, GEMM_SMEM_BYTES>>>(x, b_attn, nullptr);

    // 2) relative-position projections P[z,t,0..32]
    rel_p_kernel<<<NH * Tc / 256, 256>>>(rel);

    // 3) raw masked scores (+ zero upper triangle) into att output region
    score_mma<<<dim3(Tc / 128, Tc / 128, NH), 256, SCORE_SMEM_BYTES>>>(att);

    // 4) softmax rows in place (causal part only)
    softmax_kernel<<<dim3(Tc, NH), 256>>>(att);

    // 5) y = att @ V  (tf32 mma) -> g_y in [B,T,C]
    av_mma<<<dim3(Tc / 128, NH), 256, AV_SMEM_BYTES>>>(att);

    // 6) out_y = g_y @ w_proj + b_proj  (tf32 mma)
    mma_gemm<1024, 1><<<dim3(1024 / 128, 4096 / 128), 256, GEMM_SMEM_BYTES>>>(nullptr, b_proj, y_out);
}

// round 6
// speedup vs baseline: 2.6503x; 1.0372x over previous
#include <cuda_runtime.h>
#include <cstdint>
#include <math.h>

// Problem constants
#define Bc 2
#define Tc 2048
#define Cc 1024
#define Hc 16
#define Dc 64
#define NH (Bc * Hc)          // 32 (b,h) pairs
#define NJP 33                // only offsets -32..0 occur under causal mask

// ---------------- scratch (device globals; no allocations allowed) ----------
__device__ float g_q[NH * Tc * Dc];
__device__ float g_k[NH * Tc * Dc];
__device__ float g_v[NH * Tc * Dc];
__device__ float g_p[NH * Tc * NJP];  // P[z][t][j], j in [0,32]
__device__ float g_y[Bc * Tc * Cc];
__device__ float g_wt[3072 * 1024];   // w_attn^T  [N=3072][K=1024]
__device__ float g_wtp[1024 * 1024];  // w_proj^T  [N=1024][K=1024]

// ======================= helpers ============================================
__device__ __forceinline__ uint32_t f2tf32(float f) {
    uint32_t r;
    asm("cvt.rna.tf32.f32 %0, %1;" : "=r"(r) : "f"(f));
    return r;
}
__device__ __forceinline__ void mma_tf32_16x8x8(
    float* c, const uint32_t* a, const uint32_t* b)
{
    asm volatile(
        "mma.sync.aligned.m16n8k8.row.col.f32.tf32.tf32.f32 "
        "{%0,%1,%2,%3}, {%4,%5,%6,%7}, {%8,%9}, {%0,%1,%2,%3};"
        : "+f"(c[0]), "+f"(c[1]), "+f"(c[2]), "+f"(c[3])
        : "r"(a[0]), "r"(a[1]), "r"(a[2]), "r"(a[3]), "r"(b[0]), "r"(b[1]));
}
__device__ __forceinline__ void stcs_f2(float* p, float2 v) {
    asm volatile("st.global.cs.v2.f32 [%0], {%1, %2};" :: "l"(p), "f"(v.x), "f"(v.y) : "memory");
}
__device__ __forceinline__ void stcs_f4(float* p, float4 v) {
    asm volatile("st.global.cs.v4.f32 [%0], {%1, %2, %3, %4};"
                 :: "l"(p), "f"(v.x), "f"(v.y), "f"(v.z), "f"(v.w) : "memory");
}

// ======================= transpose: src[R][C] -> dst[C][R] ==================
__global__ __launch_bounds__(256) void transpose_kernel(
    const float* __restrict__ src, float* __restrict__ dst, int R, int C)
{
    __shared__ float t[32][33];
    int bx = blockIdx.x * 32, by = blockIdx.y * 32;
    int x = threadIdx.x, y0 = threadIdx.y;
    #pragma unroll
    for (int dy = 0; dy < 32; dy += 8)
        t[y0 + dy][x] = src[(size_t)(by + y0 + dy) * C + bx + x];
    __syncthreads();
    #pragma unroll
    for (int dy = 0; dy < 32; dy += 8)
        dst[(size_t)(bx + y0 + dy) * R + by + x] = t[x][y0 + dy];
}

// ======================= tf32 mma.sync GEMM (K=1024) ========================
#define GEMM_SMEM_BYTES (2 * 9216 * 4)
template <int N, int MODE>
__global__ __launch_bounds__(256) void mma_gemm(
    const float* __restrict__ A_in, const float* __restrict__ bias,
    float* __restrict__ out)
{
    extern __shared__ uint32_t sm[];
    const float* A  = (MODE == 0) ? A_in : g_y;
    const float* Bt = (MODE == 0) ? g_wt : g_wtp;

    const int tid = threadIdx.x, lane = tid & 31, wid = tid >> 5;
    const int bm = blockIdx.y * 128, bn = blockIdx.x * 128;
    const int wm = (wid >> 2) * 64, wn = (wid & 3) * 32;

    auto load_chunk = [&](int c, int b) {
        uint32_t* As = sm + b * 9216;
        uint32_t* Bs = As + 4608;
        const int k0 = c * 32;
        #pragma unroll
        for (int half = 0; half < 2; half++) {
            const float* src = half ? Bt + (size_t)bn * 1024 : A + (size_t)bm * 1024;
            uint32_t* dst = half ? Bs : As;
            #pragma unroll
            for (int it = 0; it < 4; it++) {
                int idx = it * 256 + tid;
                int r = idx >> 3, q = idx & 7;
                float4 v = *(const float4*)(src + (size_t)r * 1024 + k0 + q * 4);
                uint4 u;
                u.x = f2tf32(v.x); u.y = f2tf32(v.y);
                u.z = f2tf32(v.z); u.w = f2tf32(v.w);
                *(uint4*)(dst + r * 36 + q * 4) = u;
            }
        }
    };

    float acc[4][4][4] = {};

    load_chunk(0, 0);
    __syncthreads();

    for (int c = 0; c < 32; c++) {
        int cur = c & 1;
        if (c + 1 < 32) load_chunk(c + 1, cur ^ 1);

        const uint32_t* As = sm + cur * 9216;
        const uint32_t* Bs = As + 4608;
        #pragma unroll
        for (int ks = 0; ks < 4; ks++) {
            const int kc = ks * 8 + (lane & 3);
            uint32_t a[4][4], b[4][2];
            #pragma unroll
            for (int mf = 0; mf < 4; mf++) {
                int row = wm + mf * 16 + (lane >> 2);
                a[mf][0] = As[row * 36 + kc];
                a[mf][1] = As[(row + 8) * 36 + kc];
                a[mf][2] = As[row * 36 + kc + 4];
                a[mf][3] = As[(row + 8) * 36 + kc + 4];
            }
            #pragma unroll
            for (int nf = 0; nf < 4; nf++) {
                int col = wn + nf * 8 + (lane >> 2);
                b[nf][0] = Bs[col * 36 + kc];
                b[nf][1] = Bs[col * 36 + kc + 4];
            }
            #pragma unroll
            for (int mf = 0; mf < 4; mf++)
                #pragma unroll
                for (int nf = 0; nf < 4; nf++)
                    mma_tf32_16x8x8(acc[mf][nf], a[mf], b[nf]);
        }
        __syncthreads();
    }

    #pragma unroll
    for (int mf = 0; mf < 4; mf++) {
        #pragma unroll
        for (int nf = 0; nf < 4; nf++) {
            #pragma unroll
            for (int e = 0; e < 4; e++) {
                int m = bm + wm + mf * 16 + (lane >> 2) + (e >= 2 ? 8 : 0);
                int n = bn + wn + nf * 8 + 2 * (lane & 3) + (e & 1);
                float v = acc[mf][nf][e] + bias[n];
                if (MODE == 0) {
                    int b = m >> 11;
                    int t = m & 2047;
                    int sec = n >> 10;
                    int cc = n & 1023;
                    int h = cc >> 6;
                    int d = cc & 63;
                    int z = b * Hc + h;
                    float* dst = (sec == 0) ? g_q : (sec == 1 ? g_k : g_v);
                    dst[((size_t)z * Tc + t) * Dc + d] = v;
                } else {
                    out[(size_t)m * 1024 + n] = v;
                }
            }
        }
    }
}

// ---------------- P[z][t][j] = q(z,t) . rel_table[j], j in [0,32] -----------
__global__ __launch_bounds__(256) void rel_p_kernel(const float* __restrict__ rel)
{
    __shared__ float rs[NJP * Dc];
    int tid = threadIdx.x;
    for (int i = tid; i < NJP * Dc; i += 256) rs[i] = rel[i];
    __syncthreads();

    int row = blockIdx.x * 256 + tid;      // z*T + t
    float4 qv[16];
    const float4* qp = (const float4*)(g_q + (size_t)row * Dc);
    #pragma unroll
    for (int i = 0; i < 16; i++) qv[i] = qp[i];

    #pragma unroll 1
    for (int j = 0; j < NJP; j++) {
        const float4* rp = (const float4*)(rs + j * Dc);
        float s = 0.f;
        #pragma unroll
        for (int i = 0; i < 16; i++) {
            float4 b = rp[i];
            s += qv[i].x * b.x + qv[i].y * b.y + qv[i].z * b.z + qv[i].w * b.w;
        }
        g_p[(size_t)row * NJP + j] = s;
    }
}

// ================= fused attention: score + softmax + AV ====================
// One CTA per (z, 128-row q tile). Two passes over kt tiles:
//   pass 1: score tiles (tf32 mma) with online row max/sum in smem
//   pass 2: recompute scores, write normalized att (st.cs), accumulate Y=att@V
// Upper-triangle tiles zero-filled at the end. att written exactly once.
#define NQT (Tc / 128)   // 16
#define FUSED_SMEM_BYTES ((128*68 + 128*68 + 128*34 + 128*132 + 64*132 + 128*3 + 4*128) * 4)
__global__ __launch_bounds__(256) void fused_attn(float* __restrict__ att)
{
    const int qt = (NQT - 1) - blockIdx.x;   // heavy tiles first
    const int z  = blockIdx.y;
    const int q0 = qt * 128;

    extern __shared__ uint32_t sm[];
    uint32_t* Qs    = sm;                          // [128][68] tf32
    uint32_t* Ks    = Qs + 128 * 68;               // [128][68] tf32
    float*    Ps    = (float*)(Ks + 128 * 68);     // [128][34]
    uint32_t* As    = (uint32_t*)(Ps + 128 * 34);  // [128][132] tf32 att tile
    uint32_t* Vs    = As + 128 * 132;              // [64][132] tf32 V^T
    float*    m_run = (float*)(Vs + 64 * 132);     // [128]
    float*    s_run = m_run + 128;                 // [128]
    float*    sm_tm = s_run + 128;                 // [128]
    float*    wpart = sm_tm + 128;                 // [4][128]

    const int tid = threadIdx.x, lane = tid & 31, wid = tid >> 5;
    const int wm = (wid >> 2) * 64, wn = (wid & 3) * 32;   // score layout 2x4
    const int rbase = lane >> 2;                            // 0..7
    const int cpar  = lane & 3;

    // ---- load Q tile (tf32) + P table; init stats ----
    {
        const float* qg = g_q + ((size_t)z * Tc + q0) * Dc;
        #pragma unroll
        for (int it = 0; it < 8; it++) {
            int idx = it * 256 + tid;
            int r = idx >> 4, c4 = idx & 15;
            float4 v = *(const float4*)(qg + (size_t)r * Dc + c4 * 4);
            *(uint4*)(Qs + r * 68 + c4 * 4) =
                make_uint4(f2tf32(v.x), f2tf32(v.y), f2tf32(v.z), f2tf32(v.w));
        }
        for (int i = tid; i < 128 * NJP; i += 256) {
            int r = i / NJP, j = i - r * NJP;
            Ps[r * 34 + j] = g_p[((size_t)z * Tc + q0 + r) * NJP + j];
        }
        if (tid < 128) { m_run[tid] = -1e30f; s_run[tid] = 0.f; }
    }
    __syncthreads();

    auto load_K = [&](int k0) {
        const float* kg = g_k + ((size_t)z * Tc + k0) * Dc;
        #pragma unroll
        for (int it = 0; it < 8; it++) {
            int idx = it * 256 + tid;
            int r = idx >> 4, c4 = idx & 15;
            float4 v = *(const float4*)(kg + (size_t)r * Dc + c4 * 4);
            *(uint4*)(Ks + r * 68 + c4 * 4) =
                make_uint4(f2tf32(v.x), f2tf32(v.y), f2tf32(v.z), f2tf32(v.w));
        }
    };

    // score tile: v[mf][nf][e] = (QK^T + rel)*0.125, masked -> -1e30
    auto compute_score = [&](int k0, float (&v)[4][4][4]) {
        #pragma unroll
        for (int mf = 0; mf < 4; mf++)
            #pragma unroll
            for (int nf = 0; nf < 4; nf++)
                #pragma unroll
                for (int e = 0; e < 4; e++) v[mf][nf][e] = 0.f;
        #pragma unroll
        for (int ks = 0; ks < 8; ks++) {
            const int kc = ks * 8 + cpar;
            uint32_t a[4][4], b[4][2];
            #pragma unroll
            for (int mf = 0; mf < 4; mf++) {
                int row = wm + mf * 16 + rbase;
                a[mf][0] = Qs[row * 68 + kc];
                a[mf][1] = Qs[(row + 8) * 68 + kc];
                a[mf][2] = Qs[row * 68 + kc + 4];
                a[mf][3] = Qs[(row + 8) * 68 + kc + 4];
            }
            #pragma unroll
            for (int nf = 0; nf < 4; nf++) {
                int col = wn + nf * 8 + rbase;
                b[nf][0] = Ks[col * 68 + kc];
                b[nf][1] = Ks[col * 68 + kc + 4];
            }
            #pragma unroll
            for (int mf = 0; mf < 4; mf++)
                #pragma unroll
                for (int nf = 0; nf < 4; nf++)
                    mma_tf32_16x8x8(v[mf][nf], a[mf], b[nf]);
        }
        #pragma unroll
        for (int mf = 0; mf < 4; mf++) {
            #pragma unroll
            for (int e = 0; e < 4; e++) {
                int row_l = wm + mf * 16 + rbase + (e >= 2 ? 8 : 0);
                int qq = q0 + row_l;
                #pragma unroll
                for (int nf = 0; nf < 4; nf++) {
                    int kk = k0 + wn + nf * 8 + 2 * cpar + (e & 1);
                    if (kk <= qq) {
                        int dd = kk - qq;
                        if (dd < -32) dd = -32;
                        v[mf][nf][e] = (v[mf][nf][e] + Ps[row_l * 34 + dd + 32]) * 0.125f;
                    } else {
                        v[mf][nf][e] = -1e30f;
                    }
                }
            }
        }
    };

    // ============ PASS 1: online max/sum ============
    for (int kt = 0; kt <= qt; kt++) {
        load_K(kt * 128);
        __syncthreads();

        float v[4][4][4];
        compute_score(kt * 128, v);

        // per-thread row max over its 8 cols, for 8 rows (mf x half)
        float rmax[4][2];
        #pragma unroll
        for (int mf = 0; mf < 4; mf++)
            #pragma unroll
            for (int hf = 0; hf < 2; hf++) {
                float m = -1e30f;
                #pragma unroll
                for (int nf = 0; nf < 4; nf++) {
                    m = fmaxf(m, v[mf][nf][hf * 2]);
                    m = fmaxf(m, v[mf][nf][hf * 2 + 1]);
                }
                rmax[mf][hf] = m;
            }
        #pragma unroll
        for (int mf = 0; mf < 4; mf++)
            #pragma unroll
            for (int hf = 0; hf < 2; hf++) {
                float m = rmax[mf][hf];
                m = fmaxf(m, __shfl_xor_sync(0xffffffffu, m, 1));
                m = fmaxf(m, __shfl_xor_sync(0xffffffffu, m, 2));
                rmax[mf][hf] = m;
            }
        if (cpar == 0) {
            #pragma unroll
            for (int mf = 0; mf < 4; mf++)
                #pragma unroll
                for (int hf = 0; hf < 2; hf++)
                    wpart[(wid & 3) * 128 + wm + mf * 16 + rbase + hf * 8] = rmax[mf][hf];
        }
        __syncthreads();
        if (tid < 128) {
            float t = wpart[tid];
            t = fmaxf(t, wpart[128 + tid]);
            t = fmaxf(t, wpart[256 + tid]);
            t = fmaxf(t, wpart[384 + tid]);
            sm_tm[tid] = t;
        }
        __syncthreads();

        // per-thread sum of exp(v - tile_max)
        float rsum[4][2];
        #pragma unroll
        for (int mf = 0; mf < 4; mf++)
            #pragma unroll
            for (int hf = 0; hf < 2; hf++) {
                int row_l = wm + mf * 16 + rbase + hf * 8;
                float tm = sm_tm[row_l];
                float s = 0.f;
                #pragma unroll
                for (int nf = 0; nf < 4; nf++) {
                    s += __expf(v[mf][nf][hf * 2] - tm);
                    s += __expf(v[mf][nf][hf * 2 + 1] - tm);
                }
                rsum[mf][hf] = s;
            }
        #pragma unroll
        for (int mf = 0; mf < 4; mf++)
            #pragma unroll
            for (int hf = 0; hf < 2; hf++) {
                float s = rsum[mf][hf];
                s += __shfl_xor_sync(0xffffffffu, s, 1);
                s += __shfl_xor_sync(0xffffffffu, s, 2);
                rsum[mf][hf] = s;
            }
        if (cpar == 0) {
            #pragma unroll
            for (int mf = 0; mf < 4; mf++)
                #pragma unroll
                for (int hf = 0; hf < 2; hf++)
                    wpart[(wid & 3) * 128 + wm + mf * 16 + rbase + hf * 8] = rsum[mf][hf];
        }
        __syncthreads();
        if (tid < 128) {
            float ts = wpart[tid] + wpart[128 + tid] + wpart[256 + tid] + wpart[384 + tid];
            float tm = sm_tm[tid];
            float mo = m_run[tid];
            float mn = fmaxf(mo, tm);
            s_run[tid] = s_run[tid] * __expf(mo - mn) + ts * __expf(tm - mn);
            m_run[tid] = mn;
        }
        __syncthreads();
    }

    if (tid < 128) s_run[tid] = 1.0f / s_run[tid];   // now inv_sum
    __syncthreads();

    // ============ PASS 2: recompute, write att, accumulate Y ============
    const int wm2 = (wid >> 1) * 32, wn2 = (wid & 1) * 32;  // AV layout 4x2
    float accY[2][4][4] = {};

    for (int kt = 0; kt <= qt; kt++) {
        const int k0 = kt * 128;
        load_K(k0);
        __syncthreads();

        float v[4][4][4];
        compute_score(k0, v);

        // normalized att -> gmem (streaming) + As (tf32)
        #pragma unroll
        for (int mf = 0; mf < 4; mf++) {
            #pragma unroll
            for (int hf = 0; hf < 2; hf++) {
                int row_l = wm + mf * 16 + rbase + hf * 8;
                int qq = q0 + row_l;
                float mr = m_run[row_l], is = s_run[row_l];
                float* orow = att + ((size_t)z * Tc + qq) * Tc + k0;
                #pragma unroll
                for (int nf = 0; nf < 4; nf++) {
                    int col_l = wn + nf * 8 + 2 * cpar;
                    float a0 = 0.f, a1 = 0.f;
                    if (k0 + col_l <= qq)     a0 = __expf(v[mf][nf][hf * 2] - mr) * is;
                    if (k0 + col_l + 1 <= qq) a1 = __expf(v[mf][nf][hf * 2 + 1] - mr) * is;
                    stcs_f2(orow + col_l, make_float2(a0, a1));
                    *(uint2*)(As + row_l * 132 + col_l) = make_uint2(f2tf32(a0), f2tf32(a1));
                }
            }
        }

        // load V tile (transposed): Vs[d][k]
        {
            const float* vg = g_v + ((size_t)z * Tc + k0) * Dc;
            #pragma unroll
            for (int it = 0; it < 8; it++) {
                int idx = it * 256 + tid;
                int r = idx >> 4, c4 = idx & 15;
                float4 w = *(const float4*)(vg + (size_t)r * Dc + c4 * 4);
                Vs[(c4 * 4 + 0) * 132 + r] = f2tf32(w.x);
                Vs[(c4 * 4 + 1) * 132 + r] = f2tf32(w.y);
                Vs[(c4 * 4 + 2) * 132 + r] = f2tf32(w.z);
                Vs[(c4 * 4 + 3) * 132 + r] = f2tf32(w.w);
            }
        }
        __syncthreads();

        // Y += att_tile @ V_tile
        #pragma unroll
        for (int ks = 0; ks < 16; ks++) {
            const int kc = ks * 8 + cpar;
            uint32_t a[2][4], b[4][2];
            #pragma unroll
            for (int mf = 0; mf < 2; mf++) {
                int row = wm2 + mf * 16 + rbase;
                a[mf][0] = As[row * 132 + kc];
                a[mf][1] = As[(row + 8) * 132 + kc];
                a[mf][2] = As[row * 132 + kc + 4];
                a[mf][3] = As[(row + 8) * 132 + kc + 4];
            }
            #pragma unroll
            for (int nf = 0; nf < 4; nf++) {
                int col = wn2 + nf * 8 + rbase;
                b[nf][0] = Vs[col * 132 + kc];
                b[nf][1] = Vs[col * 132 + kc + 4];
            }
            #pragma unroll
            for (int mf = 0; mf < 2; mf++)
                #pragma unroll
                for (int nf = 0; nf < 4; nf++)
                    mma_tf32_16x8x8(accY[mf][nf], a[mf], b[nf]);
        }
        __syncthreads();
    }

    // zero-fill strictly-upper tiles of att for these 128 rows
    {
        const int zw = (NQT - 1 - qt) * 32;   // float4 groups per row
        const float4 zz = make_float4(0.f, 0.f, 0.f, 0.f);
        for (int i = tid; i < 128 * zw; i += 256) {
            int r = i / zw, j = i - r * zw;
            stcs_f4(att + ((size_t)z * Tc + q0 + r) * Tc + (qt + 1) * 128 + j * 4, zz);
        }
    }

    // write Y -> g_y [B,T,C]
    {
        const int b_ = z / Hc, h = z % Hc;
        #pragma unroll
        for (int mf = 0; mf < 2; mf++) {
            #pragma unroll
            for (int nf = 0; nf < 4; nf++) {
                #pragma unroll
                for (int e = 0; e < 4; e++) {
                    int row_l = wm2 + mf * 16 + rbase + (e >= 2 ? 8 : 0);
                    int d = wn2 + nf * 8 + 2 * cpar + (e & 1);
                    int q = q0 + row_l;
                    g_y[(((size_t)b_ * Tc + q) * Hc + h) * Dc + d] = accY[mf][nf][e];
                }
            }
        }
    }
}

// ---------------- launch ----------------------------------------------------
extern "C" void kernel_launch(void* const* d_in, const int* in_sizes, int n_in,
                              void* d_out, int out_size)
{
    const float* x      = (const float*)d_in[0];
    const float* w_attn = (const float*)d_in[2];
    const float* b_attn = (const float*)d_in[3];
    const float* w_proj = (const float*)d_in[4];
    const float* b_proj = (const float*)d_in[5];
    const float* rel    = (const float*)d_in[6];

    float* y_out = (float*)d_out;
    float* att   = y_out + (size_t)Bc * Tc * Cc;

    cudaFuncSetAttribute(mma_gemm<3072, 0>, cudaFuncAttributeMaxDynamicSharedMemorySize, GEMM_SMEM_BYTES);
    cudaFuncSetAttribute(mma_gemm<1024, 1>, cudaFuncAttributeMaxDynamicSharedMemorySize, GEMM_SMEM_BYTES);
    cudaFuncSetAttribute(fused_attn, cudaFuncAttributeMaxDynamicSharedMemorySize, FUSED_SMEM_BYTES);

    float* wt  = nullptr;
    float* wtp = nullptr;
    cudaGetSymbolAddress((void**)&wt, g_wt);
    cudaGetSymbolAddress((void**)&wtp, g_wtp);

    // 0) transpose weights to [N][K] K-major
    transpose_kernel<<<dim3(3072 / 32, 1024 / 32), dim3(32, 8)>>>(w_attn, wt, 1024, 3072);
    transpose_kernel<<<dim3(1024 / 32, 1024 / 32), dim3(32, 8)>>>(w_proj, wtp, 1024, 1024);

    // 1) qkv = x @ w_attn + b_attn  (tf32 mma), scattered to head layout
    mma_gemm<3072, 0><<<dim3(3072 / 128, 4096 / 128), 256, GEMM_SMEM_BYTES>>>(x, b_attn, nullptr);

    // 2) relative-position projections P[z,t,0..32]
    rel_p_kernel<<<NH * Tc / 256, 256>>>(rel);

    // 3) fused score + softmax + AV: writes att once, g_y once
    fused_attn<<<dim3(NQT, NH), 256, FUSED_SMEM_BYTES>>>(att);

    // 4) out_y = g_y @ w_proj + b_proj  (tf32 mma)
    mma_gemm<1024, 1><<<dim3(1024 / 128, 4096 / 128), 256, GEMM_SMEM_BYTES>>>(nullptr, b_proj, y_out);
}